// round 1
// baseline (speedup 1.0000x reference)
#include <cuda_runtime.h>
#include <mma.h>
#include <cstddef>

using namespace nvcuda;

// Problem constants
#define BATCH 128
#define HH 14
#define WW 14
#define CC 768
#define NHEAD 12
#define HDIM 64
#define HWSZ 196          // 14*14
#define C3 2304           // 3*C
#define MROWS 25088       // BATCH*HWSZ
#define NHEADS_TOTAL 1536 // BATCH*NHEAD

// Scratch buffers (device globals: no allocation allowed)
__device__ float g_qkv[(size_t)MROWS * C3]; // (B, HW, 3, NH, HD) natural GEMM output
__device__ float g_att[(size_t)MROWS * CC]; // (B, HW, NH, HD)

// ---------------------------------------------------------------------------
// Generic tiled tf32 GEMM with fused bias: C = A(MxK) @ B(KxN) + bias
// BM=BN=128, BK=32, 256 threads (8 warps, 2x4 layout, 64x32 per warp)
// ---------------------------------------------------------------------------
#define BM 128
#define BN 128
#define BK 32
#define ASTR 40   // 32 + 8 pad (floats)
#define BSTR 136  // 128 + 8 pad (floats)

__device__ __forceinline__ void gemm_body(
    const float* __restrict__ A, const float* __restrict__ Bm,
    const float* __restrict__ bias, float* __restrict__ C,
    int M, int N, int K)
{
    __shared__ float As[BM * ASTR];
    __shared__ float Bs[BK * BSTR];
    __shared__ float biasT[16 * BSTR];

    const int tid = threadIdx.x;
    const int m0 = blockIdx.y * BM;
    const int n0 = blockIdx.x * BN;

    // Replicated bias tile (16 identical rows) used to init accumulators.
    for (int i = tid; i < 16 * BN; i += 256) {
        int rr = i >> 7, cc = i & 127;
        biasT[rr * BSTR + cc] = bias[n0 + cc];
    }
    __syncthreads();

    const int w  = tid >> 5;
    const int wm = w >> 2;   // 0..1
    const int wn = w & 3;    // 0..3

    wmma::fragment<wmma::accumulator, 16, 16, 8, float> acc[4][2];
#pragma unroll
    for (int i = 0; i < 4; i++)
#pragma unroll
        for (int j = 0; j < 2; j++)
            wmma::load_matrix_sync(acc[i][j], &biasT[wn * 32 + j * 16], BSTR,
                                   wmma::mem_row_major);

    for (int kt = 0; kt < K; kt += BK) {
        // Stage A tile (128x32) and B tile (32x128)
#pragma unroll
        for (int p = 0; p < 4; p++) {
            int idx = tid + p * 256;
            int row = idx >> 3, c4 = (idx & 7) * 4;
            *(float4*)&As[row * ASTR + c4] =
                *(const float4*)&A[(size_t)(m0 + row) * K + kt + c4];
        }
#pragma unroll
        for (int p = 0; p < 4; p++) {
            int idx = tid + p * 256;
            int row = idx >> 5, c4 = (idx & 31) * 4;
            *(float4*)&Bs[row * BSTR + c4] =
                *(const float4*)&Bm[(size_t)(kt + row) * N + n0 + c4];
        }
        __syncthreads();

#pragma unroll
        for (int kk = 0; kk < BK; kk += 8) {
            wmma::fragment<wmma::matrix_a, 16, 16, 8, wmma::precision::tf32,
                           wmma::row_major> af[4];
            wmma::fragment<wmma::matrix_b, 16, 16, 8, wmma::precision::tf32,
                           wmma::row_major> bf[2];
#pragma unroll
            for (int i = 0; i < 4; i++) {
                wmma::load_matrix_sync(af[i], &As[(wm * 64 + i * 16) * ASTR + kk], ASTR);
#pragma unroll
                for (int e = 0; e < af[i].num_elements; e++)
                    af[i].x[e] = wmma::__float_to_tf32(af[i].x[e]);
            }
#pragma unroll
            for (int j = 0; j < 2; j++) {
                wmma::load_matrix_sync(bf[j], &Bs[kk * BSTR + wn * 32 + j * 16], BSTR);
#pragma unroll
                for (int e = 0; e < bf[j].num_elements; e++)
                    bf[j].x[e] = wmma::__float_to_tf32(bf[j].x[e]);
            }
#pragma unroll
            for (int i = 0; i < 4; i++)
#pragma unroll
                for (int j = 0; j < 2; j++)
                    wmma::mma_sync(acc[i][j], af[i], bf[j], acc[i][j]);
        }
        __syncthreads();
    }

#pragma unroll
    for (int i = 0; i < 4; i++)
#pragma unroll
        for (int j = 0; j < 2; j++)
            wmma::store_matrix_sync(
                &C[(size_t)(m0 + wm * 64 + i * 16) * N + n0 + wn * 32 + j * 16],
                acc[i][j], N, wmma::mem_row_major);
}

__global__ __launch_bounds__(256) void gemm_qkv_kernel(
    const float* __restrict__ A, const float* __restrict__ Bm,
    const float* __restrict__ bias)
{
    gemm_body(A, Bm, bias, g_qkv, MROWS, C3, CC);
}

__global__ __launch_bounds__(256) void gemm_proj_kernel(
    const float* __restrict__ Bm, const float* __restrict__ bias,
    float* __restrict__ C)
{
    gemm_body(g_att, Bm, bias, C, MROWS, CC, CC);
}

// ---------------------------------------------------------------------------
// Fused attention: one CTA per (batch, head). 256 threads.
// K,V staged in smem (stride 68 floats), per-warp processing of 4 query rows
// at a time (register blocking to amortize K/V smem reads 4x).
// Decomposed rel-pos bias: s[kh*14+kw] += dot(q,Rh[hq,kh]) + dot(q,Rw[wq,kw]).
// ---------------------------------------------------------------------------
#define KSTR 68

// smem layout sizes (floats)
#define SM_K   (224 * KSTR)   // K, padded to 224 rows (zeroed tail)
#define SM_V   (196 * KSTR)
#define SM_RH  (27 * KSTR)
#define SM_RW  (27 * KSTR)
#define SM_Q   (8 * 4 * KSTR)
#define SM_P   (8 * 4 * 200)
#define SM_REL (8 * 4 * 28)
#define ATTN_SMEM_FLOATS (SM_K + SM_V + SM_RH + SM_RW + SM_Q + SM_P + SM_REL)
#define ATTN_SMEM_BYTES (ATTN_SMEM_FLOATS * 4)

__global__ __launch_bounds__(256) void attn_kernel(
    const float* __restrict__ rph, const float* __restrict__ rpw)
{
    extern __shared__ float sm[];
    float* kS  = sm;
    float* vS  = kS + SM_K;
    float* RhS = vS + SM_V;
    float* RwS = RhS + SM_RH;
    float* qsm = RwS + SM_RW;
    float* pbf = qsm + SM_Q;
    float* rlb = pbf + SM_P;

    const int tid  = threadIdx.x;
    const int head = blockIdx.x;
    const int b = head / NHEAD;
    const int h = head % NHEAD;

    const float* gbase = g_qkv + (size_t)b * HWSZ * C3 + h * HDIM;

    // Stage K (transposed layout not needed: row-major [j][d] stride 68), V, tables
    for (int i = tid; i < HWSZ * HDIM; i += 256) {
        int j = i >> 6, d = i & 63;
        const float* p = gbase + (size_t)j * C3 + d;
        kS[j * KSTR + d] = p[768];   // K
        vS[j * KSTR + d] = p[1536];  // V
    }
    for (int i = tid; i < 28 * KSTR; i += 256) kS[196 * KSTR + i] = 0.f; // pad rows
    for (int i = tid; i < 27 * HDIM; i += 256) {
        int r = i >> 6, d = i & 63;
        RhS[r * KSTR + d] = rph[i];
        RwS[r * KSTR + d] = rpw[i];
    }
    __syncthreads();

    const int wid = tid >> 5, lane = tid & 31;
    float* qw = qsm + wid * 4 * KSTR;
    float* pw = pbf + wid * 800;
    float* rb = rlb + wid * 112;

    for (int g = wid; g < 49; g += 8) {
        const int r0 = g * 4;

        // Load 4 query rows into per-warp smem
        for (int i = lane; i < 4 * HDIM; i += 32) {
            int rr = i >> 6, d = i & 63;
            qw[rr * KSTR + d] = gbase[(size_t)(r0 + rr) * C3 + d];
        }
        __syncwarp();

        // rel-pos dots: 4 rows x (14 relh + 14 relw) = 112 length-64 dots
        for (int t = lane; t < 112; t += 32) {
            int rr = t / 28, wch = t % 28;
            int r = r0 + rr;
            const float* tab;
            int row;
            if (wch < 14) { row = r / 14 - wch + 13;        tab = RhS; }
            else          { row = r % 14 - (wch - 14) + 13; tab = RwS; }
            const float* qp = qw + rr * KSTR;
            const float* tp = tab + row * KSTR;
            float s = 0.f;
#pragma unroll
            for (int d = 0; d < 64; d++) s += qp[d] * tp[d];
            rb[rr * 28 + wch] = s;
        }
        __syncwarp();

        // QK^T: each lane owns keys j = lane + 32*jj, 4 rows at once
        float acc[4][7];
#pragma unroll
        for (int rr = 0; rr < 4; rr++)
#pragma unroll
            for (int jj = 0; jj < 7; jj++) acc[rr][jj] = 0.f;

#pragma unroll 4
        for (int d0 = 0; d0 < 64; d0 += 4) {
            float4 qv[4];
#pragma unroll
            for (int rr = 0; rr < 4; rr++)
                qv[rr] = *(const float4*)(qw + rr * KSTR + d0);
#pragma unroll
            for (int jj = 0; jj < 7; jj++) {
                int j = lane + jj * 32;  // up to 223: pad rows are zero
                float4 kv = *(const float4*)(kS + j * KSTR + d0);
#pragma unroll
                for (int rr = 0; rr < 4; rr++)
                    acc[rr][jj] += qv[rr].x * kv.x + qv[rr].y * kv.y +
                                   qv[rr].z * kv.z + qv[rr].w * kv.w;
            }
        }

        // softmax (scale 1/8, + rel bias)
        float inv[4];
#pragma unroll
        for (int rr = 0; rr < 4; rr++) {
            float m = -1e30f;
#pragma unroll
            for (int jj = 0; jj < 7; jj++) {
                int j = lane + jj * 32;
                if (j < HWSZ) {
                    float s = acc[rr][jj] * 0.125f
                            + rb[rr * 28 + j / 14]
                            + rb[rr * 28 + 14 + j % 14];
                    acc[rr][jj] = s;
                    m = fmaxf(m, s);
                }
            }
#pragma unroll
            for (int o = 16; o > 0; o >>= 1)
                m = fmaxf(m, __shfl_xor_sync(0xffffffffu, m, o));
            float lsum = 0.f;
#pragma unroll
            for (int jj = 0; jj < 7; jj++) {
                int j = lane + jj * 32;
                if (j < HWSZ) {
                    float e = __expf(acc[rr][jj] - m);
                    pw[rr * 200 + j] = e;
                    lsum += e;
                }
            }
#pragma unroll
            for (int o = 16; o > 0; o >>= 1)
                lsum += __shfl_xor_sync(0xffffffffu, lsum, o);
            inv[rr] = 1.f / lsum;
        }
        __syncwarp();

        // P @ V: each lane owns dims d = 2*lane, 2*lane+1
        float o0[4] = {0, 0, 0, 0}, o1[4] = {0, 0, 0, 0};
#pragma unroll 2
        for (int j = 0; j < HWSZ; j++) {
            float2 vv = *(const float2*)(vS + j * KSTR + 2 * lane);
#pragma unroll
            for (int rr = 0; rr < 4; rr++) {
                float p = pw[rr * 200 + j];
                o0[rr] += p * vv.x;
                o1[rr] += p * vv.y;
            }
        }

        float* gout = g_att + ((size_t)b * HWSZ + r0) * CC + h * HDIM;
#pragma unroll
        for (int rr = 0; rr < 4; rr++) {
            float2 res;
            res.x = o0[rr] * inv[rr];
            res.y = o1[rr] * inv[rr];
            *(float2*)(gout + rr * CC + 2 * lane) = res;
        }
        __syncwarp();  // protect per-warp smem buffers before next group
    }
}

// ---------------------------------------------------------------------------
extern "C" void kernel_launch(void* const* d_in, const int* in_sizes, int n_in,
                              void* d_out, int out_size)
{
    const float* x      = (const float*)d_in[0]; // (B,H,W,C) = (25088, 768)
    const float* w_qkv  = (const float*)d_in[1]; // (768, 2304)
    const float* b_qkv  = (const float*)d_in[2]; // (2304,)
    const float* rph    = (const float*)d_in[3]; // (27, 64)
    const float* rpw    = (const float*)d_in[4]; // (27, 64)
    const float* w_proj = (const float*)d_in[5]; // (768, 768)
    const float* b_proj = (const float*)d_in[6]; // (768,)
    float* out = (float*)d_out;                  // (25088, 768)

    cudaFuncSetAttribute(attn_kernel,
                         cudaFuncAttributeMaxDynamicSharedMemorySize,
                         ATTN_SMEM_BYTES);

    dim3 g1(C3 / BN, MROWS / BM);   // 18 x 196
    gemm_qkv_kernel<<<g1, 256>>>(x, w_qkv, b_qkv);

    attn_kernel<<<NHEADS_TOTAL, 256, ATTN_SMEM_BYTES>>>(rph, rpw);

    dim3 g2(CC / BN, MROWS / BM);   // 6 x 196
    gemm_proj_kernel<<<g2, 256>>>(w_proj, b_proj, out);
}

// round 2
// speedup vs baseline: 1.1779x; 1.1779x over previous
#include <cuda_runtime.h>
#include <mma.h>
#include <cstddef>
#include <cstdint>

using namespace nvcuda;

// Problem constants
#define BATCH 128
#define HH 14
#define WW 14
#define CC 768
#define NHEAD 12
#define HDIM 64
#define HWSZ 196          // 14*14
#define C3 2304           // 3*C
#define MROWS 25088       // BATCH*HWSZ
#define NHEADS_TOTAL 1536 // BATCH*NHEAD

// Scratch buffers (device globals: no allocation allowed)
__device__ float g_qkv[(size_t)MROWS * C3]; // (B, HW, 3, NH, HD)
__device__ float g_att[(size_t)MROWS * CC]; // (B, HW, NH, HD)

// ---------------------------------------------------------------------------
// cp.async helpers
// ---------------------------------------------------------------------------
__device__ __forceinline__ void cpa16(void* s, const void* g) {
    uint32_t sa = (uint32_t)__cvta_generic_to_shared(s);
    asm volatile("cp.async.cg.shared.global [%0], [%1], 16;\n" ::"r"(sa), "l"(g));
}
__device__ __forceinline__ void cpa_commit() {
    asm volatile("cp.async.commit_group;\n" ::);
}
template <int N>
__device__ __forceinline__ void cpa_wait() {
    asm volatile("cp.async.wait_group %0;\n" ::"n"(N));
}

// ---------------------------------------------------------------------------
// Pipelined tf32 GEMM with fused bias: C = A(MxK) @ B(KxN) + bias
// BM=BN=128, BK=32, 2-stage cp.async double buffering, 256 threads
// (8 warps, 2x4 layout, 64x32 per warp), 2 CTAs/SM target.
// ---------------------------------------------------------------------------
#define BM 128
#define BN 128
#define BK 32
#define ASTR 40   // 32 + 8 pad (floats); 160B row, 16B aligned
#define BSTR 136  // 128 + 8 pad (floats); 544B row, 16B aligned

#define GEMM_SMEM_BYTES (2 * BM * ASTR * 4 + 2 * BK * BSTR * 4 + 16 * BSTR * 4)

__device__ __forceinline__ void gemm_body(
    const float* __restrict__ A, const float* __restrict__ Bm,
    const float* __restrict__ bias, float* __restrict__ C,
    int M, int N, int K)
{
    extern __shared__ float smd[];
    float* As    = smd;                       // 2 stages, BM x ASTR
    float* Bs    = As + 2 * BM * ASTR;        // 2 stages, BK x BSTR
    float* biasT = Bs + 2 * BK * BSTR;        // 16 x BSTR replicated bias

    const int tid = threadIdx.x;
    const int m0 = blockIdx.y * BM;
    const int n0 = blockIdx.x * BN;

    // Replicated bias tile (16 identical rows) used to init accumulators.
    for (int i = tid; i < 16 * BN; i += 256) {
        int rr = i >> 7, cc = i & 127;
        biasT[rr * BSTR + cc] = bias[n0 + cc];
    }
    __syncthreads();

    const int w  = tid >> 5;
    const int wm = w >> 2;   // 0..1
    const int wn = w & 3;    // 0..3

    wmma::fragment<wmma::accumulator, 16, 16, 8, float> acc[4][2];
#pragma unroll
    for (int i = 0; i < 4; i++)
#pragma unroll
        for (int j = 0; j < 2; j++)
            wmma::load_matrix_sync(acc[i][j], &biasT[wn * 32 + j * 16], BSTR,
                                   wmma::mem_row_major);

    // Per-thread staging coordinates (8 x 16B cp.async per stage)
    const int arow = tid >> 3, ac4 = (tid & 7) * 4;     // A: 128 rows x 8 float4
    const int brow = tid >> 5, bc4 = (tid & 31) * 4;    // B: 32 rows x 32 float4

    const int T = K / BK;

    // Prologue: stage tile 0
    {
        const float* ag = &A[(size_t)(m0 + arow) * K + ac4];
        const float* bg = &Bm[(size_t)brow * N + n0 + bc4];
#pragma unroll
        for (int p = 0; p < 4; p++)
            cpa16(&As[(arow + p * 32) * ASTR + ac4], ag + (size_t)(p * 32) * K);
#pragma unroll
        for (int p = 0; p < 4; p++)
            cpa16(&Bs[(brow + p * 8) * BSTR + bc4], bg + (size_t)(p * 8) * N);
        cpa_commit();
    }

    for (int t = 0; t < T; t++) {
        // Prefetch tile t+1 into the other stage
        if (t + 1 < T) {
            const int st = (t + 1) & 1;
            const int kt = (t + 1) * BK;
            const float* ag = &A[(size_t)(m0 + arow) * K + kt + ac4];
            const float* bg = &Bm[(size_t)(kt + brow) * N + n0 + bc4];
            float* asd = &As[st * BM * ASTR];
            float* bsd = &Bs[st * BK * BSTR];
#pragma unroll
            for (int p = 0; p < 4; p++)
                cpa16(&asd[(arow + p * 32) * ASTR + ac4], ag + (size_t)(p * 32) * K);
#pragma unroll
            for (int p = 0; p < 4; p++)
                cpa16(&bsd[(brow + p * 8) * BSTR + bc4], bg + (size_t)(p * 8) * N);
            cpa_commit();
            cpa_wait<1>();
        } else {
            cpa_wait<0>();
        }
        __syncthreads();

        const float* asrc = &As[(t & 1) * BM * ASTR];
        const float* bsrc = &Bs[(t & 1) * BK * BSTR];

#pragma unroll
        for (int kk = 0; kk < BK; kk += 8) {
            wmma::fragment<wmma::matrix_a, 16, 16, 8, wmma::precision::tf32,
                           wmma::row_major> af[4];
            wmma::fragment<wmma::matrix_b, 16, 16, 8, wmma::precision::tf32,
                           wmma::row_major> bf[2];
#pragma unroll
            for (int i = 0; i < 4; i++) {
                wmma::load_matrix_sync(af[i], &asrc[(wm * 64 + i * 16) * ASTR + kk], ASTR);
#pragma unroll
                for (int e = 0; e < af[i].num_elements; e++)
                    af[i].x[e] = wmma::__float_to_tf32(af[i].x[e]);
            }
#pragma unroll
            for (int j = 0; j < 2; j++) {
                wmma::load_matrix_sync(bf[j], &bsrc[kk * BSTR + wn * 32 + j * 16], BSTR);
#pragma unroll
                for (int e = 0; e < bf[j].num_elements; e++)
                    bf[j].x[e] = wmma::__float_to_tf32(bf[j].x[e]);
            }
#pragma unroll
            for (int i = 0; i < 4; i++)
#pragma unroll
                for (int j = 0; j < 2; j++)
                    wmma::mma_sync(acc[i][j], af[i], bf[j], acc[i][j]);
        }
        __syncthreads();  // all warps done reading this stage before it is refilled
    }

#pragma unroll
    for (int i = 0; i < 4; i++)
#pragma unroll
        for (int j = 0; j < 2; j++)
            wmma::store_matrix_sync(
                &C[(size_t)(m0 + wm * 64 + i * 16) * N + n0 + wn * 32 + j * 16],
                acc[i][j], N, wmma::mem_row_major);
}

__global__ __launch_bounds__(256, 2) void gemm_qkv_kernel(
    const float* __restrict__ A, const float* __restrict__ Bm,
    const float* __restrict__ bias)
{
    gemm_body(A, Bm, bias, g_qkv, MROWS, C3, CC);
}

__global__ __launch_bounds__(256, 2) void gemm_proj_kernel(
    const float* __restrict__ Bm, const float* __restrict__ bias,
    float* __restrict__ C)
{
    gemm_body(g_att, Bm, bias, C, MROWS, CC, CC);
}

// ---------------------------------------------------------------------------
// Fused attention: one CTA per (batch, head). 256 threads. (unchanged)
// ---------------------------------------------------------------------------
#define KSTR 68

#define SM_K   (224 * KSTR)
#define SM_V   (196 * KSTR)
#define SM_RH  (27 * KSTR)
#define SM_RW  (27 * KSTR)
#define SM_Q   (8 * 4 * KSTR)
#define SM_P   (8 * 4 * 200)
#define SM_REL (8 * 4 * 28)
#define ATTN_SMEM_FLOATS (SM_K + SM_V + SM_RH + SM_RW + SM_Q + SM_P + SM_REL)
#define ATTN_SMEM_BYTES (ATTN_SMEM_FLOATS * 4)

__global__ __launch_bounds__(256) void attn_kernel(
    const float* __restrict__ rph, const float* __restrict__ rpw)
{
    extern __shared__ float sm[];
    float* kS  = sm;
    float* vS  = kS + SM_K;
    float* RhS = vS + SM_V;
    float* RwS = RhS + SM_RH;
    float* qsm = RwS + SM_RW;
    float* pbf = qsm + SM_Q;
    float* rlb = pbf + SM_P;

    const int tid  = threadIdx.x;
    const int head = blockIdx.x;
    const int b = head / NHEAD;
    const int h = head % NHEAD;

    const float* gbase = g_qkv + (size_t)b * HWSZ * C3 + h * HDIM;

    for (int i = tid; i < HWSZ * HDIM; i += 256) {
        int j = i >> 6, d = i & 63;
        const float* p = gbase + (size_t)j * C3 + d;
        kS[j * KSTR + d] = p[768];   // K
        vS[j * KSTR + d] = p[1536];  // V
    }
    for (int i = tid; i < 28 * KSTR; i += 256) kS[196 * KSTR + i] = 0.f;
    for (int i = tid; i < 27 * HDIM; i += 256) {
        int r = i >> 6, d = i & 63;
        RhS[r * KSTR + d] = rph[i];
        RwS[r * KSTR + d] = rpw[i];
    }
    __syncthreads();

    const int wid = tid >> 5, lane = tid & 31;
    float* qw = qsm + wid * 4 * KSTR;
    float* pw = pbf + wid * 800;
    float* rb = rlb + wid * 112;

    for (int g = wid; g < 49; g += 8) {
        const int r0 = g * 4;

        for (int i = lane; i < 4 * HDIM; i += 32) {
            int rr = i >> 6, d = i & 63;
            qw[rr * KSTR + d] = gbase[(size_t)(r0 + rr) * C3 + d];
        }
        __syncwarp();

        for (int t = lane; t < 112; t += 32) {
            int rr = t / 28, wch = t % 28;
            int r = r0 + rr;
            const float* tab;
            int row;
            if (wch < 14) { row = r / 14 - wch + 13;        tab = RhS; }
            else          { row = r % 14 - (wch - 14) + 13; tab = RwS; }
            const float* qp = qw + rr * KSTR;
            const float* tp = tab + row * KSTR;
            float s = 0.f;
#pragma unroll
            for (int d = 0; d < 64; d++) s += qp[d] * tp[d];
            rb[rr * 28 + wch] = s;
        }
        __syncwarp();

        float acc[4][7];
#pragma unroll
        for (int rr = 0; rr < 4; rr++)
#pragma unroll
            for (int jj = 0; jj < 7; jj++) acc[rr][jj] = 0.f;

#pragma unroll 4
        for (int d0 = 0; d0 < 64; d0 += 4) {
            float4 qv[4];
#pragma unroll
            for (int rr = 0; rr < 4; rr++)
                qv[rr] = *(const float4*)(qw + rr * KSTR + d0);
#pragma unroll
            for (int jj = 0; jj < 7; jj++) {
                int j = lane + jj * 32;
                float4 kv = *(const float4*)(kS + j * KSTR + d0);
#pragma unroll
                for (int rr = 0; rr < 4; rr++)
                    acc[rr][jj] += qv[rr].x * kv.x + qv[rr].y * kv.y +
                                   qv[rr].z * kv.z + qv[rr].w * kv.w;
            }
        }

        float inv[4];
#pragma unroll
        for (int rr = 0; rr < 4; rr++) {
            float m = -1e30f;
#pragma unroll
            for (int jj = 0; jj < 7; jj++) {
                int j = lane + jj * 32;
                if (j < HWSZ) {
                    float s = acc[rr][jj] * 0.125f
                            + rb[rr * 28 + j / 14]
                            + rb[rr * 28 + 14 + j % 14];
                    acc[rr][jj] = s;
                    m = fmaxf(m, s);
                }
            }
#pragma unroll
            for (int o = 16; o > 0; o >>= 1)
                m = fmaxf(m, __shfl_xor_sync(0xffffffffu, m, o));
            float lsum = 0.f;
#pragma unroll
            for (int jj = 0; jj < 7; jj++) {
                int j = lane + jj * 32;
                if (j < HWSZ) {
                    float e = __expf(acc[rr][jj] - m);
                    pw[rr * 200 + j] = e;
                    lsum += e;
                }
            }
#pragma unroll
            for (int o = 16; o > 0; o >>= 1)
                lsum += __shfl_xor_sync(0xffffffffu, lsum, o);
            inv[rr] = 1.f / lsum;
        }
        __syncwarp();

        float o0[4] = {0, 0, 0, 0}, o1[4] = {0, 0, 0, 0};
#pragma unroll 2
        for (int j = 0; j < HWSZ; j++) {
            float2 vv = *(const float2*)(vS + j * KSTR + 2 * lane);
#pragma unroll
            for (int rr = 0; rr < 4; rr++) {
                float p = pw[rr * 200 + j];
                o0[rr] += p * vv.x;
                o1[rr] += p * vv.y;
            }
        }

        float* gout = g_att + ((size_t)b * HWSZ + r0) * CC + h * HDIM;
#pragma unroll
        for (int rr = 0; rr < 4; rr++) {
            float2 res;
            res.x = o0[rr] * inv[rr];
            res.y = o1[rr] * inv[rr];
            *(float2*)(gout + rr * CC + 2 * lane) = res;
        }
        __syncwarp();
    }
}

// ---------------------------------------------------------------------------
extern "C" void kernel_launch(void* const* d_in, const int* in_sizes, int n_in,
                              void* d_out, int out_size)
{
    const float* x      = (const float*)d_in[0]; // (25088, 768)
    const float* w_qkv  = (const float*)d_in[1]; // (768, 2304)
    const float* b_qkv  = (const float*)d_in[2]; // (2304,)
    const float* rph    = (const float*)d_in[3]; // (27, 64)
    const float* rpw    = (const float*)d_in[4]; // (27, 64)
    const float* w_proj = (const float*)d_in[5]; // (768, 768)
    const float* b_proj = (const float*)d_in[6]; // (768,)
    float* out = (float*)d_out;                  // (25088, 768)

    cudaFuncSetAttribute(gemm_qkv_kernel,
                         cudaFuncAttributeMaxDynamicSharedMemorySize,
                         GEMM_SMEM_BYTES);
    cudaFuncSetAttribute(gemm_proj_kernel,
                         cudaFuncAttributeMaxDynamicSharedMemorySize,
                         GEMM_SMEM_BYTES);
    cudaFuncSetAttribute(attn_kernel,
                         cudaFuncAttributeMaxDynamicSharedMemorySize,
                         ATTN_SMEM_BYTES);

    dim3 g1(C3 / BN, MROWS / BM);   // 18 x 196
    gemm_qkv_kernel<<<g1, 256, GEMM_SMEM_BYTES>>>(x, w_qkv, b_qkv);

    attn_kernel<<<NHEADS_TOTAL, 256, ATTN_SMEM_BYTES>>>(rph, rpw);

    dim3 g2(CC / BN, MROWS / BM);   // 6 x 196
    gemm_proj_kernel<<<g2, 256, GEMM_SMEM_BYTES>>>(w_proj, b_proj, out);
}